// round 17
// baseline (speedup 1.0000x reference)
#include <cuda_runtime.h>
#include <cstdint>
#include <cfloat>

// ---------------------------------------------------------------------------
// HebbianConv2d (sm_103 baseline ISA):
//   conv as implicit GEMM on mma.sync.m16n8k16.bf16, 2-way bf16 split
//   (3 products: a0b0 + a0b1 + a1b0). KS=32 stages, 3-slot cp.async pipeline.
//   TWO k-pair patterns: (i,i+1) and shifted (i+2,i+3138) (alignment baked
//   into the stream). NEW vs R16: the q -> (boff,typ) mapping is a smem LUT
//   filled once at kernel start, removing integer divisions from the
//   per-stage issue path. WTA via hybrid near-tie exact fp32 refinement.
// ---------------------------------------------------------------------------

#define B_SZ   16
#define CIN_   256
#define COUT_  384
#define HIN_   56
#define HO_    54
#define KDIM   2304                  // 256*9
#define IMG_N  3072                  // padded local-n per image
#define NPAD   (B_SZ * IMG_N)
#define IMG_SZ (CIN_ * HIN_ * HIN_)  // 802816
#define XELEMS ((size_t)B_SZ * IMG_SZ)   // 12,845,056
#define XPW    (XELEMS + 4096)       // per pair-buffer words (+slack)
#define NS144  144                   // k16 slab count (A-prep layout)
#define NSTG   72                    // KS=32 stages
#define NQ     1152                  // k-pairs
#define AWORDS (3 * NS144 * 2 * 1024) // A packed words: 884,736
#define TAU    2e-3f                 // near-tie refinement threshold

__device__ uint32_t g_bp[4 * XPW];              // 4 paired-bf16 streams
__device__ uint32_t g_wA[AWORDS];               // A fragments, bf16-pair packed
__device__ float    g_y[(size_t)NPAD * COUT_];  // pixel-major [padded n][m]
__device__ float    g_lfbtab[768];

__device__ __forceinline__ uint32_t smem_u32(const void* p) {
    uint32_t a;
    asm("{ .reg .u64 t; cvta.to.shared.u64 t, %1; cvt.u32.u64 %0, t; }"
        : "=r"(a) : "l"(p));
    return a;
}
__device__ __forceinline__ void cp16(uint32_t dst, const void* src) {
    asm volatile("cp.async.cg.shared.global [%0], [%1], 16;"
                 :: "r"(dst), "l"(src) : "memory");
}
#define CP_COMMIT() asm volatile("cp.async.commit_group;" ::: "memory")
#define CP_WAIT1()  asm volatile("cp.async.wait_group 1;" ::: "memory")

// bf16 round-to-nearest-even via integer ops
__device__ __forceinline__ float bf16_rn(float x) {
    uint32_t u = __float_as_uint(x);
    u = (u + 0x7fffu + ((u >> 16) & 1u)) & 0xffff0000u;
    return __uint_as_float(u);
}
__device__ __forceinline__ void split2(float x, uint32_t t16[2]) {
    float b0 = bf16_rn(x);
    float b1 = bf16_rn(x - b0);
    t16[0] = __float_as_uint(b0) >> 16;
    t16[1] = __float_as_uint(b1) >> 16;
}

__device__ __forceinline__ void mma_bf16(float* d, uint4 a, uint32_t b0, uint32_t b1) {
    asm volatile(
        "mma.sync.aligned.m16n8k16.row.col.f32.bf16.bf16.f32 "
        "{%0,%1,%2,%3}, {%4,%5,%6,%7}, {%8,%9}, {%0,%1,%2,%3};"
        : "+f"(d[0]), "+f"(d[1]), "+f"(d[2]), "+f"(d[3])
        : "r"(a.x), "r"(a.y), "r"(a.z), "r"(a.w), "r"(b0), "r"(b1));
}

// ---------------------------------------------------------------------------
// k-pair scheme (2 patterns):
//   q < 768 : type0. ci=q/3, j=q%3. pair ((ci,j,0),(ci,j,1));
//             stream0 word i: (x[i], x[i+1]); boff = ci*3136 + j*56
//   q >= 768: type1. p=q-768, cp=p/3, kh=p%3. pair ((2cp,kh,2),(2cp+1,kh,2));
//             stream1 word i: (x[i+2], x[i+3138]); boff = cp*6272 + kh*56
// ---------------------------------------------------------------------------
__device__ __forceinline__ int pair_korig(int q, int e) {
    if (q < 768) { int ci = q / 3, j = q - ci * 3; return ci * 9 + j * 3 + e; }
    int p = q - 768; int cp = p / 3, kh = p - cp * 3;
    return (2 * cp + e) * 9 + kh * 3 + 2;
}

// ---------------------------------------------------------------------------
// Prep 1: 4 paired-bf16 streams, fully vectorized aligned loads.
// ---------------------------------------------------------------------------
__global__ void split_pack_kernel(const float* __restrict__ x) {
    size_t u = (size_t)blockIdx.x * 256 + threadIdx.x;
    size_t base = u * 4;
    if (base >= XELEMS) return;

    float v0[6], v3k[4];                         // v0[e] = x[base+e]
    if (base + 3144 <= XELEMS) {                 // fast path: 4 aligned float4
        float4 a = *(const float4*)(x + base);
        float4 b = *(const float4*)(x + base + 4);
        float4 c = *(const float4*)(x + base + 3136);
        float4 e4 = *(const float4*)(x + base + 3140);
        v0[0] = a.x; v0[1] = a.y; v0[2] = a.z; v0[3] = a.w;
        v0[4] = b.x; v0[5] = b.y;
        v3k[0] = c.z; v3k[1] = c.w; v3k[2] = e4.x; v3k[3] = e4.y;
    } else {
#pragma unroll
        for (int e = 0; e < 6; e++) {
            size_t i = base + e; if (i > XELEMS - 1) i = XELEMS - 1;
            v0[e] = x[i];
        }
#pragma unroll
        for (int e = 0; e < 4; e++) {
            size_t i = base + 3138 + e; if (i > XELEMS - 1) i = XELEMS - 1;
            v3k[e] = x[i];
        }
    }
    uint32_t s0[6][2], s3k[4][2];
#pragma unroll
    for (int e = 0; e < 6; e++) split2(v0[e], s0[e]);
#pragma unroll
    for (int e = 0; e < 4; e++) split2(v3k[e], s3k[e]);

#pragma unroll
    for (int t = 0; t < 2; t++) {
        uint4 w0, w2;
        uint32_t* p0 = (uint32_t*)&w0; uint32_t* p2 = (uint32_t*)&w2;
#pragma unroll
        for (int j = 0; j < 4; j++) {
            p0[j] = s0[j][t]     | (s0[j + 1][t] << 16);
            p2[j] = s0[j + 2][t] | (s3k[j][t]    << 16);
        }
        ((uint4*)(g_bp + (size_t)(t * 2 + 0) * XPW))[u] = w0;
        ((uint4*)(g_bp + (size_t)(t * 2 + 1) * XPW))[u] = w2;
    }
}

// ---------------------------------------------------------------------------
// Prep 2: A fragments. word o = ((mt*144+s144)*2+t)*1024 + f*128 + lane*4 + r
// ---------------------------------------------------------------------------
__global__ void wprep_kernel(const float* __restrict__ w) {
    int o = blockIdx.x * 256 + threadIdx.x;
    if (o >= AWORDS) return;
    int r = o & 3, lane = (o >> 2) & 31, f = (o >> 7) & 7;
    int blk = o >> 10;
    int t = blk & 1; int ms = blk >> 1; int s = ms % NS144; int mt = ms / NS144;
    int g = lane >> 2, tig = lane & 3;
    int m = mt * 128 + f * 16 + g + ((r & 1) ? 8 : 0);
    int q = s * 8 + tig + ((r & 2) ? 4 : 0);
    uint32_t wbits = 0;
#pragma unroll
    for (int e = 0; e < 2; e++) {
        int korig = pair_korig(q, e);
        uint32_t s2[2];
        split2(w[(size_t)m * KDIM + korig], s2);
        wbits |= s2[t] << (16 * e);
    }
    g_wA[o] = wbits;
}

__global__ void lfbtab_kernel() {
    int i = blockIdx.x * 256 + threadIdx.x;
    if (i < 768) {
        int d = i - 383;
        float v = 0.0f;
        if (d >= -191 && d <= 192)
            v = expf(-(float)(d * d) / (2.0f * 191.0f * 191.0f));
        g_lfbtab[i] = v;
    }
}

// ---------------------------------------------------------------------------
// Conv GEMM (bf16 3-term): CTA 128m x 128n, warp 64m x 32n, KS=32.
// Slot: A 16384B | B 2t x (16 rows x 544B) = 33792B. 3 slots + q-LUT.
// Epilogue D staging (71680B) reuses slot region (no LUT overlap).
// ---------------------------------------------------------------------------
#define SLOT_B    33792
#define LUT_OFF   (3 * SLOT_B)                  // 101376
#define SMEM_CONV (LUT_OFF + NQ * 4)            // 105984

__global__ __launch_bounds__(256, 2)
void conv_mma_kernel()
{
    extern __shared__ char smem[];
    const uint32_t sb = smem_u32(smem);
    uint32_t* qlut = (uint32_t*)(smem + LUT_OFF);

    const int tid  = threadIdx.x;
    const int lane = tid & 31;
    const int wid  = tid >> 5;
    const int gid  = lane >> 2;
    const int tig  = lane & 3;
    const int wm   = wid & 1;
    const int wn   = wid >> 1;

    const int mt   = blockIdx.x;
    const int m0   = mt * 128;
    const int bimg = blockIdx.y / 24;
    const int nl0  = (blockIdx.y - bimg * 24) * 128;
    const int imgb = bimg * IMG_SZ;

    // fill q -> (boff<<1 | typ) LUT once (divisions off the hot path)
    for (int q = tid; q < NQ; q += 256) {
        uint32_t code;
        if (q < 768) {
            int ci = q / 3, jj = q - ci * 3;
            code = ((uint32_t)(ci * 3136 + jj * 56) << 1);
        } else {
            int p = q - 768; int cp = p / 3, kh = p - cp * 3;
            code = ((uint32_t)(cp * 6272 + kh * 56) << 1) | 1u;
        }
        qlut[q] = code;
    }
    __syncthreads();

    float d[4][4][4];
#pragma unroll
    for (int i = 0; i < 4; i++)
#pragma unroll
        for (int j = 0; j < 4; j++)
#pragma unroll
            for (int q = 0; q < 4; q++) d[i][j][q] = 0.0f;

    auto issue_stage = [&](int s, int slot) {
        const uint32_t sa = sb + slot * SLOT_B;
        const uint32_t* asrc = g_wA + (size_t)(mt * NS144 + s * 2) * 2048;
#pragma unroll
        for (int j = 0; j < 4; j++) {           // A: flat 4096-word copy
            int c = j * 256 + tid;
            cp16(sa + c * 16, asrc + c * 4);
        }
#pragma unroll
        for (int j = 0; j < 4; j++) {           // B: 2t x 16 rows x 32 chunks
            int idx = j * 256 + tid;
            int t = idx >> 9, row = (idx >> 5) & 15, cin = idx & 31;
            uint32_t code = qlut[s * 16 + row];  // warp-uniform broadcast
            uint32_t typ = code & 1u;
            uint32_t boff = code >> 1;
            const uint32_t* src = g_bp + (size_t)(t * 2 + typ) * XPW
                                + imgb + boff + nl0 + cin * 4;
            cp16(sa + 16384 + t * 8704 + row * 544 + cin * 16, src);
        }
        CP_COMMIT();
    };

    auto compute_stage = [&](int slot) {
        const char* base = smem + slot * SLOT_B;
        const char* Bb = base + 16384;
#pragma unroll
        for (int slab = 0; slab < 2; slab++) {
            uint32_t bfr[2][4][2];
#pragma unroll
            for (int t = 0; t < 2; t++) {
                const char* bt = Bb + t * 8704 + slab * (8 * 544);
#pragma unroll
                for (int nf = 0; nf < 4; nf++) {
                    int nw = (wn * 32 + nf * 8 + gid) * 4;
                    bfr[t][nf][0] = *(const uint32_t*)(bt + tig * 544 + nw);
                    bfr[t][nf][1] = *(const uint32_t*)(bt + (tig + 4) * 544 + nw);
                }
            }
            const char* Ab = base + slab * 8192;
#pragma unroll
            for (int fh = 0; fh < 2; fh++) {
#pragma unroll
                for (int ta = 0; ta < 2; ta++) {
                    uint4 afr[2];
#pragma unroll
                    for (int f2 = 0; f2 < 2; f2++) {
                        int f = wm * 4 + fh * 2 + f2;
                        afr[f2] = *(const uint4*)(Ab + ta * 4096 + f * 512 + lane * 16);
                    }
                    const int ntb = (ta == 0) ? 2 : 1;   // (0,0),(0,1),(1,0)
#pragma unroll
                    for (int tb = 0; tb < 2; tb++) {
                        if (tb < ntb) {
#pragma unroll
                            for (int f2 = 0; f2 < 2; f2++)
#pragma unroll
                                for (int nf = 0; nf < 4; nf++)
                                    mma_bf16(d[fh * 2 + f2][nf], afr[f2],
                                             bfr[tb][nf][0], bfr[tb][nf][1]);
                        }
                    }
                }
            }
        }
    };

    issue_stage(0, 0);
    issue_stage(1, 1);
    for (int s = 0; s < NSTG; s++) {
        CP_WAIT1();
        __syncthreads();
        if (s + 2 < NSTG) issue_stage(s + 2, (s + 2) % 3);
        else CP_COMMIT();
        compute_stage(s % 3);
    }

    // ---- epilogue: D -> smem [n][140] -> coalesced g_y[n][m] ----
    __syncthreads();
    float* ds = (float*)smem;
#pragma unroll
    for (int fm = 0; fm < 4; fm++) {
#pragma unroll
        for (int nf = 0; nf < 4; nf++) {
            int mb = wm * 64 + fm * 16 + gid;
            int nb = wn * 32 + nf * 8 + 2 * tig;
            ds[nb * 140 + mb]           = d[fm][nf][0];
            ds[(nb + 1) * 140 + mb]     = d[fm][nf][1];
            ds[nb * 140 + mb + 8]       = d[fm][nf][2];
            ds[(nb + 1) * 140 + mb + 8] = d[fm][nf][3];
        }
    }
    __syncthreads();
    const int n0g = bimg * IMG_N + nl0;
#pragma unroll
    for (int q = 0; q < 16; q++) {
        int idx = q * 256 + tid;
        int n  = idx >> 5;
        int m4 = idx & 31;
        float4 v = *(const float4*)(ds + n * 140 + m4 * 4);
        *(float4*)(g_y + (size_t)(n0g + n) * COUT_ + m0 + m4 * 4) = v;
    }
}

// ---------------------------------------------------------------------------
// Exact fp32 re-evaluation (sequential k = ci,kh,kw; fmaf chain)
// ---------------------------------------------------------------------------
__device__ float refine_dot(const float* __restrict__ x, const float* __restrict__ w,
                            int b, int h, int wp, int c) {
    const float* wr = w + (size_t)c * KDIM;
    const float* xb = x + ((size_t)b * CIN_) * (HIN_ * HIN_) + h * HIN_ + wp;
    float acc = 0.0f;
    for (int ci = 0; ci < CIN_; ci++) {
        const float* xr = xb + ci * (HIN_ * HIN_);
        const float* wc = wr + ci * 9;
#pragma unroll
        for (int kh = 0; kh < 3; kh++)
#pragma unroll
            for (int kw = 0; kw < 3; kw++)
                acc = fmaf(xr[kh * HIN_ + kw], wc[kh * 3 + kw], acc);
    }
    return acc;
}

// ---------------------------------------------------------------------------
// WTA + Gaussian LFB gating (27 pixels/block) with near-tie refinement
// ---------------------------------------------------------------------------
#define SYP 388

__global__ __launch_bounds__(256)
void wta_lfb_kernel(const float* __restrict__ xg, const float* __restrict__ wg,
                    float* __restrict__ out) {
    __shared__ float sy[27 * SYP];
    __shared__ float stab[768];
    __shared__ int   wcnt[27];
    __shared__ int   wlist[27][4];
    __shared__ int   ccnt[27];
    __shared__ int   cand[27][8];

    const int tid = threadIdx.x;
    const int b   = blockIdx.z;
    const int h   = blockIdx.y;
    const int w0  = blockIdx.x * 27;

    const size_t base = ((size_t)b * IMG_N + h * HIN_ + w0) * COUT_;

    for (int i4 = tid; i4 < 27 * 96; i4 += 256) {
        float4 v = *(const float4*)(g_y + base + (size_t)i4 * 4);
        int j  = i4 / 96;
        int c4 = i4 - j * 96;
        *(float4*)&sy[j * SYP + c4 * 4] = v;
    }
    if (tid < 192) {
        float4 t = *(const float4*)(g_lfbtab + tid * 4);
        *(float4*)&stab[tid * 4] = t;
    }
    if (tid < 27) { wcnt[tid] = 0; ccnt[tid] = 0; }
    __syncthreads();

    const int wd   = tid >> 5;
    const int lane = tid & 31;
    for (int j = wd; j < 27; j += 8) {
        const float* p = &sy[j * SYP];
        float mx = -FLT_MAX;
#pragma unroll
        for (int q = 0; q < 12; q++) mx = fmaxf(mx, p[lane + q * 32]);
#pragma unroll
        for (int o = 16; o; o >>= 1) mx = fmaxf(mx, __shfl_xor_sync(0xffffffffu, mx, o));
        const float thr = mx - TAU;
#pragma unroll
        for (int q = 0; q < 12; q++) {
            int c = lane + q * 32;
            if (p[c] >= thr) {
                int pos = atomicAdd(&ccnt[j], 1);
                if (pos < 8) cand[j][pos] = c;
            }
        }
        __syncwarp();
        int nc = ccnt[j]; if (nc > 8) nc = 8;
        if (nc == 1) {
            if (lane == 0) { wlist[j][0] = cand[j][0]; wcnt[j] = 1; }
        } else {
            float rv = -FLT_MAX;
            if (lane < nc) rv = refine_dot(xg, wg, b, h, w0 + j, cand[j][lane]);
            float rmx = rv;
#pragma unroll
            for (int o = 16; o; o >>= 1) rmx = fmaxf(rmx, __shfl_xor_sync(0xffffffffu, rmx, o));
            if (lane < nc && rv == rmx) {
                int pos = atomicAdd(&wcnt[j], 1);
                if (pos < 4) wlist[j][pos] = cand[j][lane];
            }
        }
    }
    __syncthreads();

    int c = tid / 27;
    int j = tid - c * 27;
    const size_t obase = (((size_t)b * COUT_) * HO_ + h) * HO_ + w0;
    while (c < COUT_) {
        float yv = sy[j * SYP + c];
        int nw = wcnt[j];
        float lfb = stab[wlist[j][0] - c + 383];
        if (nw > 1) {
            if (nw > 4) nw = 4;
            for (int t = 1; t < nw; t++)
                lfb += stab[wlist[j][t] - c + 383];
            lfb = fminf(lfb, 1.0f);
        }
        out[obase + (size_t)c * (HO_ * HO_) + j] = lfb * yv;
        c += 9; j += 13;
        if (j >= 27) { j -= 27; c += 1; }
    }
}

// ---------------------------------------------------------------------------
extern "C" void kernel_launch(void* const* d_in, const int* in_sizes, int n_in,
                              void* d_out, int out_size) {
    const float* x = (const float*)d_in[0];   // (16,256,56,56)
    const float* w = (const float*)d_in[1];   // (384,256,3,3)
    float* out = (float*)d_out;               // (16,384,54,54)

    cudaFuncSetAttribute(conv_mma_kernel,
                         cudaFuncAttributeMaxDynamicSharedMemorySize, SMEM_CONV);

    split_pack_kernel<<<(unsigned)((XELEMS / 4 + 255) / 256), 256>>>(x);
    wprep_kernel<<<(AWORDS + 255) / 256, 256>>>(w);
    lfbtab_kernel<<<3, 256>>>();              // conv at launch idx 3 (ncu -s 5)

    dim3 g1(3, B_SZ * 24);                    // m fastest -> B reuse in L2
    conv_mma_kernel<<<g1, 256, SMEM_CONV>>>();

    dim3 g2(2, HO_, B_SZ);
    wta_lfb_kernel<<<g2, 256>>>(x, w, out);
}